// round 3
// baseline (speedup 1.0000x reference)
#include <cuda_runtime.h>
#include <math.h>

// ---------------------------------------------------------------------------
// LinearAttention fused pipeline, fp32, f32x2-FFMA CUDA-core GEMMs.
//
//   x      [16,256,64,64]  fp32   (b, c, h, w) ; pix = h*w = 4096
//   w_qkv  [768,256]              rows 0..255 = q, 256..511 = k, 512..767 = v
//   w_out  [256,256]
//   gamma/beta [256]
//
// Kernel 1: qkv GEMM (M=65536, N=768, K=256) + elu1 + per-tile k/v reductions
// Kernel 2: finalize scale[b,c] = sum(kk*v)/max(sum(kk),1e-6)
// Kernel 3: out GEMM (M=65536, N=256, K=256) with scale folded into A,
//           fused channel LayerNorm epilogue.
// ---------------------------------------------------------------------------

using u64 = unsigned long long;

__device__ __forceinline__ u64 pack2(float x, float y) {
    u64 r; asm("mov.b64 %0, {%1, %2};" : "=l"(r) : "f"(x), "f"(y)); return r;
}
__device__ __forceinline__ void unpack2(u64 v, float &x, float &y) {
    asm("mov.b64 {%0, %1}, %2;" : "=f"(x), "=f"(y) : "l"(v));
}
// packed dual-FMA: d.lo += a.lo*b.lo ; d.hi += a.hi*b.hi  (full-rate fp32 path)
__device__ __forceinline__ void ffma2(u64 &d, u64 a, u64 b) {
    asm("fma.rn.f32x2 %0, %1, %2, %0;" : "+l"(d) : "l"(a), "l"(b));
}

__device__ __forceinline__ float elu1(float v) {
    // F.elu(v)+1 : v+1 for v>=0, exp(v) for v<0
    return v > 0.0f ? v + 1.0f : expf(v);
}

// ------------------------- scratch (device globals) ------------------------
#define NB   16
#define NC   256
#define NPIX 4096
#define PTILES_PER_B 32            // 4096 / 128
#define NTILES (NB * PTILES_PER_B) // 512

__device__ float g_qk[(size_t)NB * NC * NPIX];   // 64 MB: elu1(q), layout [b][c][pix]
__device__ float g_part_kv[NTILES][NC];
__device__ float g_part_kk[NTILES][NC];
__device__ float g_scale[NB * NC];

// ===========================================================================
// Kernel 1: QKV GEMM + elu + partial reductions
//   grid (8, 512): blockIdx.x = channel group g (32 channels, x3 sections),
//                  blockIdx.y = pixel tile t (128 pixels)
//   block: 256 threads = 16 pixThreads (x8 pix) * 16 ocThreads (x2 oc)
// ===========================================================================
__global__ __launch_bounds__(256, 2)
void k_qkv(const float* __restrict__ x, const float* __restrict__ w_qkv)
{
    __shared__ alignas(16) float As[32][128];      // [k][pix]
    __shared__ alignas(16) float Bs[3][32][33];    // [sec][k][oc] pad->conflict-free

    const int g    = blockIdx.x;            // 0..7
    const int t    = blockIdx.y;            // 0..511
    const int b    = t >> 5;
    const int p0   = (t & 31) << 7;         // pixel base within batch
    const int tid  = threadIdx.x;
    const int pixT = tid & 15;              // 0..15
    const int ocT  = tid >> 4;              // 0..15

    u64 acc[3][2][4];                       // [sec][oc j][pixel-pair i]
#pragma unroll
    for (int s = 0; s < 3; s++)
#pragma unroll
        for (int j = 0; j < 2; j++)
#pragma unroll
            for (int i = 0; i < 4; i++) acc[s][j][i] = 0ull;

    const float* xb = x + (size_t)b * NC * NPIX + p0;

    for (int kc = 0; kc < 256; kc += 32) {
        // ---- load A tile: 32 K-rows x 128 pixels (coalesced 512B rows) ----
#pragma unroll
        for (int r = 0; r < 4; r++) {
            int f = tid + 256 * r;          // 0..1023
            int k = f >> 5, q = f & 31;
            float4 v = *(const float4*)(xb + (size_t)(kc + k) * NPIX + q * 4);
            *(float4*)&As[k][q * 4] = v;
        }
        // ---- load B tile: 3 sections x 32 oc rows x 32 K (transpose) ----
#pragma unroll
        for (int r = 0; r < 3; r++) {
            int f    = tid + 256 * r;       // 0..767
            int oall = f >> 3, q = f & 7;
            int s    = oall >> 5, ol = oall & 31;
            int grow = s * 256 + g * 32 + ol;
            float4 v = *(const float4*)(w_qkv + (size_t)grow * 256 + kc + q * 4);
            Bs[s][q * 4 + 0][ol] = v.x;
            Bs[s][q * 4 + 1][ol] = v.y;
            Bs[s][q * 4 + 2][ol] = v.z;
            Bs[s][q * 4 + 3][ol] = v.w;
        }
        __syncthreads();

#pragma unroll 8
        for (int kk = 0; kk < 32; kk++) {
            u64 av[4];
#pragma unroll
            for (int i = 0; i < 4; i++)
                av[i] = *(const u64*)&As[kk][32 * i + 2 * pixT];  // LDS.64, conflict-free
#pragma unroll
            for (int s = 0; s < 3; s++) {
#pragma unroll
                for (int j = 0; j < 2; j++) {
                    float bs = Bs[s][kk][ocT * 2 + j];            // warp-broadcast
                    u64 bv = pack2(bs, bs);
#pragma unroll
                    for (int i = 0; i < 4; i++) ffma2(acc[s][j][i], av[i], bv);
                }
            }
        }
        __syncthreads();
    }

    // -------- epilogue: qk -> scratch, (kk*v, kk) -> per-tile partials -----
    const int cbase = g * 32 + ocT * 2;
#pragma unroll
    for (int j = 0; j < 2; j++) {
        const int c = cbase + j;
        float* dst = g_qk + ((size_t)(b * NC + c)) * NPIX + p0;
        float skv = 0.0f, skk = 0.0f;
#pragma unroll
        for (int i = 0; i < 4; i++) {
            float q0, q1, k0, k1, v0, v1;
            unpack2(acc[0][j][i], q0, q1);
            unpack2(acc[1][j][i], k0, k1);
            unpack2(acc[2][j][i], v0, v1);
            float2 qo; qo.x = elu1(q0); qo.y = elu1(q1);
            *(float2*)(dst + 32 * i + 2 * pixT) = qo;             // 64B/warp-seg stores
            float ek0 = elu1(k0), ek1 = elu1(k1);
            skv += ek0 * v0 + ek1 * v1;
            skk += ek0 + ek1;
        }
        // reduce over the 16 pixThreads (lanes of a half-warp)
#pragma unroll
        for (int off = 1; off < 16; off <<= 1) {
            skv += __shfl_xor_sync(0xFFFFFFFFu, skv, off);
            skk += __shfl_xor_sync(0xFFFFFFFFu, skk, off);
        }
        if (pixT == 0) {
            g_part_kv[t][c] = skv;
            g_part_kk[t][c] = skk;
        }
    }
}

// ===========================================================================
// Kernel 2: finalize scale[b][c]   (deterministic serial sum over 32 tiles)
// ===========================================================================
__global__ void k_scale_fin()
{
    int idx = blockIdx.x * 256 + threadIdx.x;   // 0..4095
    int b = idx >> 8, c = idx & 255;
    float skv = 0.0f, skk = 0.0f;
#pragma unroll
    for (int i = 0; i < PTILES_PER_B; i++) {
        skv += g_part_kv[b * PTILES_PER_B + i][c];
        skk += g_part_kk[b * PTILES_PER_B + i][c];
    }
    g_scale[idx] = skv / fmaxf(skk, 1e-6f);
}

// ===========================================================================
// Kernel 3: out GEMM + fused LayerNorm
//   grid 1024: 64-pixel tiles; block 256 = 8 pixThreads(x8 pix) * 32 ocT(x8 oc)
// ===========================================================================
__global__ __launch_bounds__(256, 2)
void k_out(const float* __restrict__ w_out, const float* __restrict__ gamma,
           const float* __restrict__ beta, float* __restrict__ out)
{
    __shared__ alignas(16) float As[32][64];
    __shared__ alignas(16) float Bs[32][257];
    __shared__ float sscale[256], sgamma[256], sbeta[256];
    __shared__ float smu[64], srstd[64];

    const int blk  = blockIdx.x;
    const int b    = blk >> 6;
    const int p0   = (blk & 63) << 6;
    const int tid  = threadIdx.x;
    const int pixT = tid & 7;               // 0..7
    const int ocT  = tid >> 3;              // 0..31
    const int lane = tid & 31;
    const int warp = tid >> 5;              // 0..7

    sscale[tid] = g_scale[b * NC + tid];
    sgamma[tid] = gamma[tid];
    sbeta[tid]  = beta[tid];
    __syncthreads();

    u64 acc[8][4];                          // [oc j][pixel-pair i]
#pragma unroll
    for (int j = 0; j < 8; j++)
#pragma unroll
        for (int i = 0; i < 4; i++) acc[j][i] = 0ull;

    const float* qb = g_qk + (size_t)b * NC * NPIX + p0;

    for (int kc = 0; kc < 256; kc += 32) {
        // A: 32 K-rows x 64 pixels, scale folded in
#pragma unroll
        for (int r = 0; r < 2; r++) {
            int f = tid + 256 * r;          // 0..511
            int k = f >> 4, q = f & 15;
            float4 v = *(const float4*)(qb + (size_t)(kc + k) * NPIX + q * 4);
            float s = sscale[kc + k];
            v.x *= s; v.y *= s; v.z *= s; v.w *= s;
            *(float4*)&As[k][q * 4] = v;
        }
        // B: 256 oc rows x 32 K (transpose into [k][oc], pad 257)
#pragma unroll
        for (int r = 0; r < 8; r++) {
            int f = tid + 256 * r;          // 0..2047
            int o = f >> 3, q = f & 7;
            float4 v = *(const float4*)(w_out + (size_t)o * 256 + kc + q * 4);
            Bs[q * 4 + 0][o] = v.x;
            Bs[q * 4 + 1][o] = v.y;
            Bs[q * 4 + 2][o] = v.z;
            Bs[q * 4 + 3][o] = v.w;
        }
        __syncthreads();

#pragma unroll 8
        for (int kk = 0; kk < 32; kk++) {
            u64 av[4];
#pragma unroll
            for (int i = 0; i < 4; i++)
                av[i] = *(const u64*)&As[kk][16 * i + 2 * pixT];
#pragma unroll
            for (int j = 0; j < 8; j++) {
                float bs = Bs[kk][ocT * 8 + j];
                u64 bv = pack2(bs, bs);
#pragma unroll
                for (int i = 0; i < 4; i++) ffma2(acc[j][i], av[i], bv);
            }
        }
        __syncthreads();
    }

    // ---------------- fused LayerNorm over the 256 channels ----------------
    // per-thread partial sums for its 8 pixels across its 8 channels
    float ps[4][2], pss[4][2];
#pragma unroll
    for (int i = 0; i < 4; i++) { ps[i][0] = ps[i][1] = 0.0f; pss[i][0] = pss[i][1] = 0.0f; }
#pragma unroll
    for (int j = 0; j < 8; j++)
#pragma unroll
        for (int i = 0; i < 4; i++) {
            float v0, v1; unpack2(acc[j][i], v0, v1);
            ps[i][0] += v0;  pss[i][0] += v0 * v0;
            ps[i][1] += v1;  pss[i][1] += v1 * v1;
        }
    // combine the 4 ocThreads living in this warp (lane strides 8, 16)
#pragma unroll
    for (int off = 8; off < 32; off <<= 1)
#pragma unroll
        for (int i = 0; i < 4; i++) {
            ps[i][0]  += __shfl_xor_sync(0xFFFFFFFFu, ps[i][0],  off);
            ps[i][1]  += __shfl_xor_sync(0xFFFFFFFFu, ps[i][1],  off);
            pss[i][0] += __shfl_xor_sync(0xFFFFFFFFu, pss[i][0], off);
            pss[i][1] += __shfl_xor_sync(0xFFFFFFFFu, pss[i][1], off);
        }
    // deterministic cross-warp reduce through smem (alias the A tile)
    float (*redA)[64] = (float(*)[64])&As[0][0];     // 8 x 64
    float (*redB)[64] = (float(*)[64])&As[16][0];    // 8 x 64
    __syncthreads();                                  // GEMM reads of As done
    if (lane < 8) {                                   // lane == pixT, ocT-group 0
#pragma unroll
        for (int i = 0; i < 4; i++) {
            int p = 16 * i + 2 * lane;
            redA[warp][p]     = ps[i][0];
            redA[warp][p + 1] = ps[i][1];
            redB[warp][p]     = pss[i][0];
            redB[warp][p + 1] = pss[i][1];
        }
    }
    __syncthreads();
    if (tid < 64) {
        float s = 0.0f, ss = 0.0f;
#pragma unroll
        for (int w = 0; w < 8; w++) { s += redA[w][tid]; ss += redB[w][tid]; }
        float mu  = s * (1.0f / 256.0f);
        float var = ss * (1.0f / 256.0f) - mu * mu;
        smu[tid]   = mu;
        srstd[tid] = rsqrtf(var + 1e-5f);
    }
    __syncthreads();

    // normalized writes: 64B contiguous per 8-lane pixel group -> coalesced
    float* ob = out + (size_t)b * NC * NPIX + p0;
#pragma unroll
    for (int j = 0; j < 8; j++) {
        int oc = ocT * 8 + j;
        float gm = sgamma[oc], bt = sbeta[oc];
        float* dst = ob + (size_t)oc * NPIX;
#pragma unroll
        for (int i = 0; i < 4; i++) {
            int p = 16 * i + 2 * pixT;
            float v0, v1; unpack2(acc[j][i], v0, v1);
            float2 o2;
            o2.x = (v0 - smu[p])     * srstd[p]     * gm + bt;
            o2.y = (v1 - smu[p + 1]) * srstd[p + 1] * gm + bt;
            *(float2*)(dst + p) = o2;
        }
    }
}

// ===========================================================================
extern "C" void kernel_launch(void* const* d_in, const int* in_sizes, int n_in,
                              void* d_out, int out_size)
{
    const float* x      = (const float*)d_in[0];
    const float* w_qkv  = (const float*)d_in[1];
    const float* w_out  = (const float*)d_in[2];
    const float* gamma  = (const float*)d_in[3];
    const float* beta   = (const float*)d_in[4];
    float* out = (float*)d_out;

    dim3 g1(8, NTILES);                 // 8 channel groups x 512 pixel tiles
    k_qkv<<<g1, 256>>>(x, w_qkv);
    k_scale_fin<<<16, 256>>>();
    k_out<<<1024, 256>>>(w_out, gamma, beta, out);
}